// round 17
// baseline (speedup 1.0000x reference)
#include <cuda_runtime.h>
#include <cuda_bf16.h>
#include <stdint.h>
#include <math.h>

#define N_ROWS 65536
#define P_ROWS 2048
#define D_DIM  512

#define BM 128
#define BN 128
#define STAGES 3
#define K_CHUNKS 8             // 64 bf16 (128B) per row per chunk
#define CHUNK_BYTES 16384      // 128 rows x 128B, contiguous + pre-swizzled in gmem
#define STAGE_BYTES 32768      // A chunk + B chunk
#define SM_BAR (STAGES * STAGE_BYTES)      // 98304
#define SMEM_TOTAL (SM_BAR + 128)

// ---------------- scratch (static device globals; no runtime allocation) ----
__device__ float g_xsq[N_ROWS];
__device__ float g_psq[P_ROWS];
// tiled+swizzled bf16 images: [tile][kc][128 x 128B], byte-addressed
__device__ unsigned char g_ebf[(size_t)N_ROWS * D_DIM * 2];
__device__ unsigned char g_pbf[(size_t)P_ROWS * D_DIM * 2];

// ---------------- PTX helpers ----------------------------------------------
__device__ __forceinline__ uint32_t smem_u32(const void* p) {
    uint32_t a;
    asm("{ .reg .u64 t; cvta.to.shared.u64 t, %1; cvt.u32.u64 %0, t; }" : "=r"(a) : "l"(p));
    return a;
}

#define MBARRIER_INIT(addr, cnt) \
    asm volatile("mbarrier.init.shared.b64 [%0], %1;" :: "r"((uint32_t)(addr)), "r"((uint32_t)(cnt)) : "memory")
#define MBARRIER_ARRIVE(addr) \
    asm volatile("mbarrier.arrive.shared.b64 _, [%0];" :: "r"((uint32_t)(addr)) : "memory")
#define MBARRIER_EXPECT_TX(addr, bytes) \
    asm volatile("mbarrier.arrive.expect_tx.shared.b64 _, [%0], %1;" :: "r"((uint32_t)(addr)), "r"((uint32_t)(bytes)) : "memory")

#define MBARRIER_WAIT_PARITY(mbar_smem_addr, phase_parity) do { \
    uint32_t _mbar = (uint32_t)(mbar_smem_addr); \
    uint32_t _parity = (uint32_t)(phase_parity); \
    uint32_t _done; \
    asm volatile( \
        "{\n\t.reg .pred p;\n\t" \
        "mbarrier.try_wait.parity.acquire.cta.shared::cta.b64 p, [%1], %2;\n\t" \
        "selp.b32 %0, 1, 0, p;\n\t}" \
        : "=r"(_done) : "r"(_mbar), "r"(_parity) : "memory"); \
    if (!_done) { \
        asm volatile( \
            "{\n\t.reg .pred P1;\n\t" \
            "WAIT_LOOP_%=:\n\t" \
            "mbarrier.try_wait.parity.acquire.cta.shared::cta.b64 P1, [%0], %1, 0x989680;\n\t" \
            "@P1 bra.uni WAIT_DONE_%=;\n\t" \
            "bra.uni WAIT_LOOP_%=;\n\t" \
            "WAIT_DONE_%=:\n\t}" \
            :: "r"(_mbar), "r"(_parity) : "memory"); \
    } \
} while(0)

// one-shot 16KB bulk copy gmem -> smem, completion via mbarrier tx bytes
#define CP_BULK16K(dst_smem, src_gmem, mbar) \
    asm volatile("{\n\t.reg .u64 g;\n\tcvta.to.global.u64 g, %1;\n\t" \
        "cp.async.bulk.shared::cluster.global.mbarrier::complete_tx::bytes [%0], [g], %2, [%3];\n\t}" \
        :: "r"((uint32_t)(dst_smem)), "l"(src_gmem), "n"(16384), "r"((uint32_t)(mbar)) : "memory")

#define LDMATRIX_X4(r0, r1, r2, r3, addr) \
    asm volatile("ldmatrix.sync.aligned.m8n8.x4.shared.b16 {%0,%1,%2,%3}, [%4];" \
        : "=r"(r0), "=r"(r1), "=r"(r2), "=r"(r3) : "r"(addr))

#define MMA_16816_BF16(c0, c1, c2, c3, a0, a1, a2, a3, b0, b1) \
    asm volatile("mma.sync.aligned.m16n8k16.row.col.f32.bf16.bf16.f32 " \
        "{%0,%1,%2,%3}, {%4,%5,%6,%7}, {%8,%9}, {%0,%1,%2,%3};" \
        : "+f"(c0), "+f"(c1), "+f"(c2), "+f"(c3) \
        : "r"(a0), "r"(a1), "r"(a2), "r"(a3), "r"(b0), "r"(b1))

// ---------------- convert fp32 -> bf16 tiled+swizzled + row norms -----------
// One warp per row. Row's 512 bf16 = 64 16B-units; kc = u>>3 (8 chunks of
// 128B/row), c = u&7; stored at tile_base + kc*16384 + r*128 + ((c^(r&7))<<4).
__global__ void convert_all_kernel(const float* __restrict__ e,
                                   const float* __restrict__ p) {
    int warp = (blockIdx.x * blockDim.x + threadIdx.x) >> 5;
    int lane = threadIdx.x & 31;

    const float* src;
    unsigned char* dstbase;
    float* sq;
    int row;
    if (warp < N_ROWS) {
        src = e; dstbase = g_ebf; sq = g_xsq; row = warp;
    } else if (warp < N_ROWS + P_ROWS) {
        src = p; dstbase = g_pbf; sq = g_psq; row = warp - N_ROWS;
    } else return;

    const int t = row >> 7;
    const int r = row & 127;
    const float4* rp = reinterpret_cast<const float4*>(src + (size_t)row * D_DIM);

    float s = 0.f;
    uint4 un[2];
#pragma unroll
    for (int hu = 0; hu < 2; hu++) {
        uint32_t w[4];
#pragma unroll
        for (int j = 0; j < 2; j++) {
            float4 v = rp[lane * 4 + hu * 2 + j];
            s += v.x * v.x + v.y * v.y + v.z * v.z + v.w * v.w;
            __nv_bfloat162 lo = __floats2bfloat162_rn(v.x, v.y);
            __nv_bfloat162 hi = __floats2bfloat162_rn(v.z, v.w);
            w[j * 2 + 0] = *reinterpret_cast<uint32_t*>(&lo);
            w[j * 2 + 1] = *reinterpret_cast<uint32_t*>(&hi);
        }
        un[hu] = make_uint4(w[0], w[1], w[2], w[3]);
    }
#pragma unroll
    for (int o = 16; o > 0; o >>= 1) s += __shfl_xor_sync(0xffffffffu, s, o);
    if (lane == 0) sq[row] = s;

    unsigned char* tb = dstbase + (size_t)t * (K_CHUNKS * CHUNK_BYTES);
#pragma unroll
    for (int hu = 0; hu < 2; hu++) {
        int u = lane * 2 + hu;
        int kc = u >> 3, c = u & 7;
        size_t off = (size_t)kc * CHUNK_BYTES + r * 128 + (((c ^ (r & 7))) << 4);
        *reinterpret_cast<uint4*>(tb + off) = un[hu];
    }
}

// ---------------- main GEMM + distance kernel -------------------------------
// 128 threads = 4 warps, warp grid 2x2, warp tile 64x64, CTA tile 128x128,
// 3-stage 16KB bulk-copy ring fed by thread 0, mbarrier full/empty handshake.
__global__ __launch_bounds__(128, 2) void gemm_mma_kernel(float* __restrict__ C) {
    extern __shared__ char smem[];
    const uint32_t sb = smem_u32(smem);

    const int tid  = threadIdx.x;
    const int wid  = tid >> 5;
    const int lane = tid & 31;
    const int wm = wid >> 1;   // 0..1 (64-row slab)
    const int wn = wid & 1;    // 0..1 (64-col slab)

    const int mt = blockIdx.y;            // m-tile (128 rows)
    const int pt = blockIdx.x;            // p-tile (128 cols)
    const int bRow = mt * BM;
    const int bCol = pt * BN;

    const unsigned char* gAt = g_ebf + (size_t)mt * (K_CHUNKS * CHUNK_BYTES);
    const unsigned char* gBt = g_pbf + (size_t)pt * (K_CHUNKS * CHUNK_BYTES);

    const uint32_t fullb  = sb + SM_BAR;        // 3 x 8B
    const uint32_t emptyb = sb + SM_BAR + 64;   // 3 x 8B

    if (tid == 0) {
#pragma unroll
        for (int s = 0; s < STAGES; s++) {
            MBARRIER_INIT(fullb + s * 8, 1);    // tx-based (expect_tx arrive)
            MBARRIER_INIT(emptyb + s * 8, 4);   // one arrive per warp
        }
    }
    __syncthreads();

    // prologue: issue stages 0..1
    if (tid == 0) {
#pragma unroll
        for (int s = 0; s < STAGES - 1; s++) {
            MBARRIER_EXPECT_TX(fullb + s * 8, STAGE_BYTES);
            CP_BULK16K(sb + s * STAGE_BYTES, gAt + (size_t)s * CHUNK_BYTES, fullb + s * 8);
            CP_BULK16K(sb + s * STAGE_BYTES + CHUNK_BYTES, gBt + (size_t)s * CHUNK_BYTES, fullb + s * 8);
        }
    }

    // loop-invariant ldmatrix addressing: addr = stage + rowOff + ((kU^sx)<<4)
    const int lmRow = lane & 15;
    const int lmHi  = lane >> 4;            // 16B-unit select within k16 step
    uint32_t aOff[4], sxA[4];
#pragma unroll
    for (int i = 0; i < 4; i++) {
        int r = wm * 64 + i * 16 + lmRow;
        aOff[i] = r * 128;
        sxA[i] = r & 7;
    }
    uint32_t bOff[4], sxB[4];
#pragma unroll
    for (int jp = 0; jp < 4; jp++) {
        int r = wn * 64 + jp * 16 + lmRow;
        bOff[jp] = r * 128;
        sxB[jp] = r & 7;
    }

    float acc[4][8][4];
#pragma unroll
    for (int i = 0; i < 4; i++)
#pragma unroll
        for (int j = 0; j < 8; j++)
#pragma unroll
            for (int q = 0; q < 4; q++) acc[i][j][q] = 0.f;

#pragma unroll
    for (int k = 0; k < K_CHUNKS; k++) {
        // producer: refill stage k+2 (all indices compile-time constants)
        if (tid == 0) {
            const int kl = k + STAGES - 1;
            if (kl < K_CHUNKS) {
                const int ls = kl % STAGES;
                const int lround = kl / STAGES;
                if (lround >= 1)
                    MBARRIER_WAIT_PARITY(emptyb + ls * 8, (lround - 1) & 1);
                MBARRIER_EXPECT_TX(fullb + ls * 8, STAGE_BYTES);
                CP_BULK16K(sb + ls * STAGE_BYTES, gAt + (size_t)kl * CHUNK_BYTES, fullb + ls * 8);
                CP_BULK16K(sb + ls * STAGE_BYTES + CHUNK_BYTES, gBt + (size_t)kl * CHUNK_BYTES, fullb + ls * 8);
            }
        }

        const int slot = k % STAGES;
        MBARRIER_WAIT_PARITY(fullb + slot * 8, (k / STAGES) & 1);

        const uint32_t stA = sb + slot * STAGE_BYTES;
        const uint32_t stB = stA + CHUNK_BYTES;

#pragma unroll
        for (int kk = 0; kk < 4; kk++) {          // four k16 steps per 128B chunk
            const uint32_t kU = kk * 2 + lmHi;

            uint32_t a[4][4];
#pragma unroll
            for (int i = 0; i < 4; i++) {
                uint32_t addr = stA + aOff[i] + ((kU ^ sxA[i]) << 4);
                LDMATRIX_X4(a[i][0], a[i][1], a[i][2], a[i][3], addr);
            }
            uint32_t b[4][4];
#pragma unroll
            for (int jp = 0; jp < 4; jp++) {
                uint32_t addr = stB + bOff[jp] + ((kU ^ sxB[jp]) << 4);
                LDMATRIX_X4(b[jp][0], b[jp][1], b[jp][2], b[jp][3], addr);
            }
#pragma unroll
            for (int i = 0; i < 4; i++) {
#pragma unroll
                for (int j = 0; j < 8; j++) {
                    int jp = j >> 1, h = j & 1;
                    MMA_16816_BF16(acc[i][j][0], acc[i][j][1], acc[i][j][2], acc[i][j][3],
                                   a[i][0], a[i][1], a[i][2], a[i][3],
                                   b[jp][h], b[jp][2 + h]);
                }
            }
        }
        if (lane == 0) MBARRIER_ARRIVE(emptyb + slot * 8);
    }

    // ---- epilogue: d = xs + ps - 2*cross ; out = -sqrt(max(d,0)) ----
    const int r0 = lane >> 2;        // 0..7
    const int cq = (lane & 3) * 2;   // 0,2,4,6

    float ps0[8], ps1[8];
#pragma unroll
    for (int j = 0; j < 8; j++) {
        int gc = bCol + wn * 64 + j * 8 + cq;
        ps0[j] = g_psq[gc];
        ps1[j] = g_psq[gc + 1];
    }

#pragma unroll
    for (int i = 0; i < 4; i++) {
#pragma unroll
        for (int h = 0; h < 2; h++) {
            int grow = bRow + wm * 64 + i * 16 + r0 + h * 8;
            float xs = g_xsq[grow];
            float* crow = C + (size_t)grow * P_ROWS + bCol + wn * 64;
#pragma unroll
            for (int j = 0; j < 8; j++) {
                float c0 = acc[i][j][h * 2 + 0];
                float c1 = acc[i][j][h * 2 + 1];
                float d0 = fmaf(-2.f, c0, xs + ps0[j]);
                float d1 = fmaf(-2.f, c1, xs + ps1[j]);
                float2 o;
                o.x = (d0 > 0.f) ? (-d0 * rsqrtf(d0)) : 0.f;
                o.y = (d1 > 0.f) ? (-d1 * rsqrtf(d1)) : 0.f;
                *reinterpret_cast<float2*>(crow + j * 8 + cq) = o;
            }
        }
    }
}

// ---------------- launch ----------------------------------------------------
extern "C" void kernel_launch(void* const* d_in, const int* in_sizes, int n_in,
                              void* d_out, int out_size) {
    const float* emb   = (const float*)d_in[0];  // [N, D]
    const float* proto = (const float*)d_in[1];  // [P, D]
    float* out = (float*)d_out;                  // [N, P]

    cudaFuncSetAttribute(gemm_mma_kernel,
                         cudaFuncAttributeMaxDynamicSharedMemorySize, SMEM_TOTAL);

    convert_all_kernel<<<(N_ROWS + P_ROWS) / 8, 256>>>(emb, proto);

    dim3 grid(P_ROWS / BN, N_ROWS / BM);  // (16, 512): columns fastest -> A reuse in L2
    gemm_mma_kernel<<<grid, 128, SMEM_TOTAL>>>(out);
}